// round 14
// baseline (speedup 1.0000x reference)
#include <cuda_runtime.h>
#include <cuda_fp16.h>
#include <math.h>
#include <stdint.h>

// Shapes (fixed): x[8,4096,512] f32, w_qkv[512,1536], b_qkv[1536],
// w_proj[512,512], b_proj[512], out[8,4096,512] f32.
constexpr int B_   = 8;
constexpr int N_   = 4096;
constexpr int C_   = 512;
constexpr int H_   = 8;
constexpr int D_   = 64;
constexpr int MTOK = B_ * N_;   // 32768
constexpr int C3   = 3 * C_;    // 1536
constexpr int KB   = 512;       // GEMM K (fp16 operands both sides)

// ------------------------- device scratch (static) -------------------------
__device__ __half g_xs[(size_t)MTOK * KB];    // x   -> fp16   (A of qkv gemm)
__device__ __half g_ms[(size_t)MTOK * KB];    // mid -> fp16   (A of proj gemm)
__device__ __half g_wq[(size_t)C3 * KB];      // w_qkv^T  fp16 [n][k]
__device__ __half g_wp[(size_t)C_ * KB];      // w_proj^T fp16 [n][k]
__device__ __half g_qkvh[(size_t)MTOK * C3];  // qkv fp16 [tok][1536]
__device__ float g_attn[B_ * H_ * D_ * D_];   // raw logits (softmax fused in v_attn)

// ----------------------------- helpers ------------------------------------
__device__ __forceinline__ uint32_t smem_u32(const void* p) {
    uint32_t a;
    asm("{ .reg .u64 t; cvta.to.shared.u64 t, %1; cvt.u32.u64 %0, t; }"
        : "=r"(a) : "l"(p));
    return a;
}
__device__ __forceinline__ uint32_t packh(float a, float b) {
    __half2 p = __floats2half2_rn(a, b);
    return *(uint32_t*)&p;
}

#define CP_ASYNC16(dst_u32, src_ptr) \
    asm volatile("cp.async.cg.shared.global [%0], [%1], 16;" \
        :: "r"(dst_u32), "l"(src_ptr))
#define CP_COMMIT()  asm volatile("cp.async.commit_group;")
#define CP_WAIT0()   asm volatile("cp.async.wait_group 0;" ::: "memory")

__device__ __forceinline__ void ldmatrix_x4(uint32_t* r, uint32_t addr) {
    asm volatile("ldmatrix.sync.aligned.m8n8.x4.shared.b16 {%0,%1,%2,%3}, [%4];"
        : "=r"(r[0]), "=r"(r[1]), "=r"(r[2]), "=r"(r[3]) : "r"(addr));
}
__device__ __forceinline__ void mma_f16(float* c, const uint32_t* a,
                                        uint32_t b0, uint32_t b1) {
    asm volatile(
        "mma.sync.aligned.m16n8k16.row.col.f32.f16.f16.f32 "
        "{%0,%1,%2,%3}, {%4,%5,%6,%7}, {%8,%9}, {%0,%1,%2,%3};"
        : "+f"(c[0]), "+f"(c[1]), "+f"(c[2]), "+f"(c[3])
        : "r"(a[0]), "r"(a[1]), "r"(a[2]), "r"(a[3]), "r"(b0), "r"(b1));
}

// =========================== prep kernels ==================================
// x fp32 -> fp16
__global__ __launch_bounds__(256) void split_x_kernel(const float* __restrict__ x)
{
    size_t fid = (size_t)blockIdx.x * 256 + threadIdx.x;  // MTOK*128 float4s
    size_t t = fid >> 7;
    int c4 = (int)(fid & 127);
    float4 v = ((const float4*)x)[fid];
    uint2 hi;
    hi.x = packh(v.x, v.y); hi.y = packh(v.z, v.w);
    *(uint2*)(g_xs + t * KB + c4 * 4) = hi;
}

// W[512][Ntot] -> out[n][k] transposed fp16
__global__ __launch_bounds__(256) void split_w_kernel(const float* __restrict__ W,
                                                      __half* __restrict__ out,
                                                      int Ntot)
{
    __shared__ float tile[32][33];
    int n0 = blockIdx.x * 32, k0 = blockIdx.y * 32;
    int tx = threadIdx.x & 31, ty = threadIdx.x >> 5;  // ty 0..7
    #pragma unroll
    for (int i = 0; i < 32; i += 8)
        tile[ty + i][tx] = W[(size_t)(k0 + ty + i) * Ntot + n0 + tx];
    __syncthreads();
    #pragma unroll
    for (int i = 0; i < 32; i += 8) {
        float v = tile[tx][ty + i];              // = W[k0+tx][n0+ty+i]
        out[(size_t)(n0 + ty + i) * KB + k0 + tx] = __float2half_rn(v);
    }
}

// ================== mma.sync fp16 GEMM, 128x128 CTA tile ===================
// C[M,Ntot] = A[M,512]fp16 @ B[Ntot,512]fp16^T + bias; output fp32 or fp16.
// 8 warps (2x4), warp tile 64x32, BK=64 (8 chunks), 2-stage cp.async.
// smem pitch 144B = 9 x 16B (odd multiple of 16B) -> conflict-free ldmatrix.
constexpr int BKC    = 64;                      // k per chunk
constexpr int NKC    = KB / BKC;                // 8 k-chunks
constexpr int PITCH  = 144;                     // bytes per smem row
constexpr int TILE_B = 128 * PITCH;             // 18432 bytes per tile
constexpr int STAGE_B = 2 * TILE_B;             // A + B = 36864
constexpr int GEMM_SMEM = 2 * STAGE_B;          // 73728 bytes

template <bool HOUT>
__global__ __launch_bounds__(256, 2) void gemm_mma_kernel(
    const __half* __restrict__ A, const __half* __restrict__ Bm,
    const float* __restrict__ bias, void* __restrict__ Cout, int Ntot)
{
    extern __shared__ __align__(16) __half smem[];

    const int tid  = threadIdx.x;
    const int lane = tid & 31;
    const int wid  = tid >> 5;
    const int wr   = wid & 1;     // warp row (0-1): 64 rows each
    const int wc   = wid >> 1;    // warp col (0-3): 32 cols each
    const size_t rowA0 = (size_t)blockIdx.y * 128;
    const size_t rowB0 = (size_t)blockIdx.x * 128;

    const __half* Abase = A + rowA0 * KB;
    const __half* Bbase = Bm + rowB0 * KB;

    const uint32_t s_base = smem_u32(smem);

    // copy: per stage 128 rows x 128B for A and B = 2048 x 16B chunks, 8/thread
    auto stage_copy = [&](int kc, int buf) {
        const uint32_t st = s_base + buf * STAGE_B;
        const int ko = kc * BKC;
        #pragma unroll
        for (int i = 0; i < 4; i++) {            // A: idx in [0,1024)
            int idx = tid + i * 256;
            int r = idx >> 3, c = idx & 7;
            const __half* g = Abase + (size_t)r * KB + ko + c * 8;
            CP_ASYNC16(st + (uint32_t)(r * PITCH + c * 16), g);
        }
        #pragma unroll
        for (int i = 0; i < 4; i++) {            // B
            int idx = tid + i * 256;
            int r = idx >> 3, c = idx & 7;
            const __half* g = Bbase + (size_t)r * KB + ko + c * 8;
            CP_ASYNC16(st + TILE_B + (uint32_t)(r * PITCH + c * 16), g);
        }
        CP_COMMIT();
    };

    float acc[4][4][4];
    #pragma unroll
    for (int i = 0; i < 4; i++)
        #pragma unroll
        for (int j = 0; j < 4; j++)
            #pragma unroll
            for (int k = 0; k < 4; k++) acc[i][j][k] = 0.f;

    // ldmatrix source coordinates
    const int a_row = wr * 64 + (lane & 7) + ((lane >> 3) & 1) * 8;
    const int a_k8  = ((lane >> 4) & 1) * 8;
    const int b_row = wc * 32 + (lane & 7) + ((lane >> 4) & 1) * 8;
    const int b_k8  = ((lane >> 3) & 1) * 8;

    stage_copy(0, 0);
    CP_WAIT0();
    __syncthreads();

    #pragma unroll 1
    for (int kc = 0; kc < NKC; kc++) {
        const int buf = kc & 1;
        if (kc + 1 < NKC) stage_copy(kc + 1, buf ^ 1);

        const uint32_t ab = s_base + buf * STAGE_B;
        const uint32_t bb = ab + TILE_B;
        #pragma unroll
        for (int ks = 0; ks < 4; ks++) {         // 4 x k16 per chunk
            uint32_t bfrg[2][4];
            #pragma unroll
            for (int nj2 = 0; nj2 < 2; nj2++)
                ldmatrix_x4(bfrg[nj2],
                    bb + (uint32_t)((b_row + nj2 * 16) * PITCH + (ks * 16 + b_k8) * 2));
            uint32_t afr[4][4];
            #pragma unroll
            for (int mi = 0; mi < 4; mi++)
                ldmatrix_x4(afr[mi],
                    ab + (uint32_t)((a_row + mi * 16) * PITCH + (ks * 16 + a_k8) * 2));
            #pragma unroll
            for (int mi = 0; mi < 4; mi++) {
                #pragma unroll
                for (int nj = 0; nj < 4; nj++) {
                    uint32_t b0 = bfrg[nj >> 1][(nj & 1) * 2];
                    uint32_t b1 = bfrg[nj >> 1][(nj & 1) * 2 + 1];
                    mma_f16(acc[mi][nj], afr[mi], b0, b1);
                }
            }
        }
        if (kc + 1 < NKC) CP_WAIT0();
        __syncthreads();
    }

    // epilogue: + bias; fp32 or fp16 stores
    #pragma unroll
    for (int mi = 0; mi < 4; mi++) {
        size_t r0 = rowA0 + wr * 64 + mi * 16 + (lane >> 2);
        size_t r1 = r0 + 8;
        #pragma unroll
        for (int nj = 0; nj < 4; nj++) {
            size_t col = rowB0 + wc * 32 + nj * 8 + (lane & 3) * 2;
            float b0 = __ldg(&bias[col]), b1 = __ldg(&bias[col + 1]);
            float c00 = acc[mi][nj][0] + b0, c01 = acc[mi][nj][1] + b1;
            float c10 = acc[mi][nj][2] + b0, c11 = acc[mi][nj][3] + b1;
            if (HOUT) {
                __half* Ch = (__half*)Cout;
                *(uint32_t*)(Ch + r0 * (size_t)Ntot + col) = packh(c00, c01);
                *(uint32_t*)(Ch + r1 * (size_t)Ntot + col) = packh(c10, c11);
            } else {
                float* Cf = (float*)Cout;
                float2 v0 = {c00, c01};
                float2 v1 = {c10, c11};
                *(float2*)(Cf + r0 * (size_t)Ntot + col) = v0;
                *(float2*)(Cf + r1 * (size_t)Ntot + col) = v1;
            }
        }
    }
}

__global__ void zero_attn_kernel()
{
    int i = blockIdx.x * blockDim.x + threadIdx.x;
    if (i < B_ * H_ * D_ * D_) g_attn[i] = 0.f;
}

// ========== attn[bh,d,e] = sum_n q~[n,d] k~[n,e], norms fused inline =======
// 64 threads/block (8x8 thread grid), 8x8 output tile per thread: 4x higher
// arithmetic intensity on smem reads than the old 4x4 layout.
__global__ __launch_bounds__(64) void attn_qk_kernel()
{
    constexpr int TOKS = 32;
    __shared__ __align__(16) float qs[TOKS][68];
    __shared__ __align__(16) float ks[TOKS][68];
    const int tid = threadIdx.x;
    const int tx = tid & 7;         // e group (8 cols)
    const int ty = tid >> 3;        // d group (8 rows)
    const int bh = blockIdx.y, b = bh >> 3, hh = bh & 7;
    const int tok_base = blockIdx.x * 256;

    float acc[8][8];
    #pragma unroll
    for (int i = 0; i < 8; i++)
        #pragma unroll
        for (int j = 0; j < 8; j++) acc[i][j] = 0.f;

    for (int sub = 0; sub < 256; sub += TOKS) {
        #pragma unroll
        for (int it = 0; it < 8; it++) {
            int fid = tid + it * 64;            // 0..511
            int tl = fid >> 4, d4 = fid & 15;
            int t = b * N_ + tok_base + sub + tl;
            const __half* base = g_qkvh + (size_t)t * C3 + hh * D_ + d4 * 4;
            uint2 qh = *(const uint2*)base;
            uint2 kh = *(const uint2*)(base + C_);
            float2 q01 = __half22float2(*(__half2*)&qh.x);
            float2 q23 = __half22float2(*(__half2*)&qh.y);
            float2 k01 = __half22float2(*(__half2*)&kh.x);
            float2 k23 = __half22float2(*(__half2*)&kh.y);
            float sq = q01.x * q01.x + q01.y * q01.y + q23.x * q23.x + q23.y * q23.y;
            float sk = k01.x * k01.x + k01.y * k01.y + k23.x * k23.x + k23.y * k23.y;
            #pragma unroll
            for (int o = 8; o; o >>= 1) {
                sq += __shfl_xor_sync(0xFFFFFFFFu, sq, o);
                sk += __shfl_xor_sync(0xFFFFFFFFu, sk, o);
            }
            float rq = 0.125f * rsqrtf(fmaxf(sq, 1e-12f));  // includes d^-0.5
            float rk = rsqrtf(fmaxf(sk, 1e-12f));
            float4 qv = {q01.x * rq, q01.y * rq, q23.x * rq, q23.y * rq};
            float4 kv = {k01.x * rk, k01.y * rk, k23.x * rk, k23.y * rk};
            *(float4*)&qs[tl][d4 * 4] = qv;
            *(float4*)&ks[tl][d4 * 4] = kv;
        }
        __syncthreads();
        #pragma unroll 2
        for (int tok = 0; tok < TOKS; tok++) {
            float4 q0 = *(const float4*)&qs[tok][ty * 8];
            float4 q1 = *(const float4*)&qs[tok][ty * 8 + 4];
            float4 k0 = *(const float4*)&ks[tok][tx * 8];
            float4 k1 = *(const float4*)&ks[tok][tx * 8 + 4];
            float rd[8] = {q0.x, q0.y, q0.z, q0.w, q1.x, q1.y, q1.z, q1.w};
            float re[8] = {k0.x, k0.y, k0.z, k0.w, k1.x, k1.y, k1.z, k1.w};
            #pragma unroll
            for (int i = 0; i < 8; i++)
                #pragma unroll
                for (int j = 0; j < 8; j++)
                    acc[i][j] = fmaf(rd[i], re[j], acc[i][j]);
        }
        __syncthreads();
    }
    float* out = g_attn + (size_t)bh * D_ * D_;
    #pragma unroll
    for (int i = 0; i < 8; i++)
        #pragma unroll
        for (int j = 0; j < 8; j++)
            atomicAdd(&out[(ty * 8 + i) * D_ + tx * 8 + j], acc[i][j]);
}

// == mid = v @ softmax(attn): warp-parallel fused softmax; fp16 out ==========
__global__ __launch_bounds__(256) void v_attn_kernel()
{
    __shared__ __align__(16) float at[D_][D_];
    __shared__ __align__(16) float vs[D_][D_];
    const int tid = threadIdx.x;
    const int lane = tid & 31;
    const int wrp  = tid >> 5;       // 8 warps
    const int bh = blockIdx.y, b = bh >> 3, hh = bh & 7;
    const int tok0 = blockIdx.x * 64;

    const float* ap = g_attn + (size_t)bh * D_ * D_;
    #pragma unroll
    for (int it = 0; it < 4; it++) {
        int fid = tid + it * 256;
        ((float4*)at)[fid] = ((const float4*)ap)[fid];
    }
    #pragma unroll
    for (int it = 0; it < 4; it++) {
        int fid = tid + it * 256;
        int tl = fid >> 4, d4 = fid & 15;
        int t = b * N_ + tok0 + tl;
        uint2 vh = *(const uint2*)(g_qkvh + (size_t)t * C3 + 2 * C_ + hh * D_ + d4 * 4);
        float2 v01 = __half22float2(*(__half2*)&vh.x);
        float2 v23 = __half22float2(*(__half2*)&vh.y);
        float4 vv = {v01.x, v01.y, v23.x, v23.y};
        *(float4*)&vs[tl][d4 * 4] = vv;
    }
    __syncthreads();

    // fused softmax: warp-per-row group, lanes parallel over e (conflict-free)
    #pragma unroll
    for (int i = 0; i < 8; i++) {
        int d = wrp * 8 + i;
        float e0 = at[d][lane], e1 = at[d][lane + 32];
        float m = fmaxf(e0, e1);
        #pragma unroll
        for (int o = 16; o; o >>= 1) m = fmaxf(m, __shfl_xor_sync(0xFFFFFFFFu, m, o));
        float x0 = __expf(e0 - m), x1 = __expf(e1 - m);
        float s = x0 + x1;
        #pragma unroll
        for (int o = 16; o; o >>= 1) s += __shfl_xor_sync(0xFFFFFFFFu, s, o);
        float inv = 1.f / s;
        at[d][lane]      = x0 * inv;
        at[d][lane + 32] = x1 * inv;
    }
    __syncthreads();

    const int rg = tid >> 4, cg = tid & 15;
    float acc[4][4];
    #pragma unroll
    for (int i = 0; i < 4; i++)
        #pragma unroll
        for (int j = 0; j < 4; j++) acc[i][j] = 0.f;

    #pragma unroll 8
    for (int d = 0; d < D_; d++) {
        float4 a4 = *(const float4*)&at[d][cg * 4];
        float ae[4] = {a4.x, a4.y, a4.z, a4.w};
        #pragma unroll
        for (int i = 0; i < 4; i++) {
            float va = vs[rg * 4 + i][d];
            #pragma unroll
            for (int j = 0; j < 4; j++)
                acc[i][j] = fmaf(va, ae[j], acc[i][j]);
        }
    }

    #pragma unroll
    for (int i = 0; i < 4; i++) {
        int t = b * N_ + tok0 + rg * 4 + i;
        uint2 hi;
        hi.x = packh(acc[i][0], acc[i][1]);
        hi.y = packh(acc[i][2], acc[i][3]);
        *(uint2*)(g_ms + (size_t)t * KB + hh * D_ + cg * 4) = hi;
    }
}

// ================================ launch ===================================
extern "C" void kernel_launch(void* const* d_in, const int* in_sizes, int n_in,
                              void* d_out, int out_size)
{
    const float* x      = (const float*)d_in[0];
    const float* w_qkv  = (const float*)d_in[1];
    const float* b_qkv  = (const float*)d_in[2];
    const float* w_proj = (const float*)d_in[3];
    const float* b_proj = (const float*)d_in[4];
    float* out = (float*)d_out;

    __half* xs; cudaGetSymbolAddress((void**)&xs, g_xs);
    __half* ms; cudaGetSymbolAddress((void**)&ms, g_ms);
    __half* wq; cudaGetSymbolAddress((void**)&wq, g_wq);
    __half* wp; cudaGetSymbolAddress((void**)&wp, g_wp);
    __half* qkvh; cudaGetSymbolAddress((void**)&qkvh, g_qkvh);

    cudaFuncSetAttribute(gemm_mma_kernel<true>,
                         cudaFuncAttributeMaxDynamicSharedMemorySize, GEMM_SMEM);
    cudaFuncSetAttribute(gemm_mma_kernel<false>,
                         cudaFuncAttributeMaxDynamicSharedMemorySize, GEMM_SMEM);

    // prep: fp16 conversions (+ zero logits, off the critical GEMM path)
    split_x_kernel<<<(MTOK * (C_ / 4)) / 256, 256>>>(x);
    split_w_kernel<<<dim3(C3 / 32, C_ / 32), 256>>>(w_qkv, wq, C3);
    split_w_kernel<<<dim3(C_ / 32, C_ / 32), 256>>>(w_proj, wp, C_);
    zero_attn_kernel<<<(B_ * H_ * D_ * D_ + 255) / 256, 256>>>();

    // qkv = x @ w_qkv + b_qkv  (fp16 mma.sync, fp16 output)
    gemm_mma_kernel<true><<<dim3(C3 / 128, MTOK / 128), 256, GEMM_SMEM>>>(
        xs, wq, b_qkv, qkvh, C3);

    attn_qk_kernel<<<dim3(N_ / 256, B_ * H_), 64>>>();
    v_attn_kernel<<<dim3(N_ / 64, B_ * H_), 256>>>();

    // out = mid @ w_proj + b_proj  (fp16 mma.sync, fp32 output)
    gemm_mma_kernel<false><<<dim3(C_ / 128, MTOK / 128), 256, GEMM_SMEM>>>(
        ms, wp, b_proj, out, C_);
}

// round 15
// speedup vs baseline: 1.0030x; 1.0030x over previous
#include <cuda_runtime.h>
#include <cuda_fp16.h>
#include <math.h>
#include <stdint.h>

// Shapes (fixed): x[8,4096,512] f32, w_qkv[512,1536], b_qkv[1536],
// w_proj[512,512], b_proj[512], out[8,4096,512] f32.
constexpr int B_   = 8;
constexpr int N_   = 4096;
constexpr int C_   = 512;
constexpr int H_   = 8;
constexpr int D_   = 64;
constexpr int MTOK = B_ * N_;   // 32768
constexpr int C3   = 3 * C_;    // 1536
constexpr int KB   = 512;       // GEMM K (fp16 operands both sides)

// ------------------------- device scratch (static) -------------------------
__device__ __half g_xs[(size_t)MTOK * KB];    // x   -> fp16   (A of qkv gemm)
__device__ __half g_ms[(size_t)MTOK * KB];    // mid -> fp16   (A of proj gemm)
__device__ __half g_wq[(size_t)C3 * KB];      // w_qkv^T  fp16 [n][k]
__device__ __half g_wp[(size_t)C_ * KB];      // w_proj^T fp16 [n][k]
__device__ __half g_qkvh[(size_t)MTOK * C3];  // qkv fp16 [tok][1536]
__device__ float g_attn[B_ * H_ * D_ * D_];   // raw logits (softmax fused in v_attn)

// ----------------------------- helpers ------------------------------------
__device__ __forceinline__ uint32_t smem_u32(const void* p) {
    uint32_t a;
    asm("{ .reg .u64 t; cvta.to.shared.u64 t, %1; cvt.u32.u64 %0, t; }"
        : "=r"(a) : "l"(p));
    return a;
}
__device__ __forceinline__ uint32_t packh(float a, float b) {
    __half2 p = __floats2half2_rn(a, b);
    return *(uint32_t*)&p;
}

#define CP_ASYNC16(dst_u32, src_ptr) \
    asm volatile("cp.async.cg.shared.global [%0], [%1], 16;" \
        :: "r"(dst_u32), "l"(src_ptr))
#define CP_COMMIT()  asm volatile("cp.async.commit_group;")
#define CP_WAIT0()   asm volatile("cp.async.wait_group 0;" ::: "memory")

__device__ __forceinline__ void ldmatrix_x4(uint32_t* r, uint32_t addr) {
    asm volatile("ldmatrix.sync.aligned.m8n8.x4.shared.b16 {%0,%1,%2,%3}, [%4];"
        : "=r"(r[0]), "=r"(r[1]), "=r"(r[2]), "=r"(r[3]) : "r"(addr));
}
__device__ __forceinline__ void mma_f16(float* c, const uint32_t* a,
                                        uint32_t b0, uint32_t b1) {
    asm volatile(
        "mma.sync.aligned.m16n8k16.row.col.f32.f16.f16.f32 "
        "{%0,%1,%2,%3}, {%4,%5,%6,%7}, {%8,%9}, {%0,%1,%2,%3};"
        : "+f"(c[0]), "+f"(c[1]), "+f"(c[2]), "+f"(c[3])
        : "r"(a[0]), "r"(a[1]), "r"(a[2]), "r"(a[3]), "r"(b0), "r"(b1));
}

// =========================== prep kernels ==================================
// x fp32 -> fp16
__global__ __launch_bounds__(256) void split_x_kernel(const float* __restrict__ x)
{
    size_t fid = (size_t)blockIdx.x * 256 + threadIdx.x;  // MTOK*128 float4s
    size_t t = fid >> 7;
    int c4 = (int)(fid & 127);
    float4 v = ((const float4*)x)[fid];
    uint2 hi;
    hi.x = packh(v.x, v.y); hi.y = packh(v.z, v.w);
    *(uint2*)(g_xs + t * KB + c4 * 4) = hi;
}

// W[512][Ntot] -> out[n][k] transposed fp16
__global__ __launch_bounds__(256) void split_w_kernel(const float* __restrict__ W,
                                                      __half* __restrict__ out,
                                                      int Ntot)
{
    __shared__ float tile[32][33];
    int n0 = blockIdx.x * 32, k0 = blockIdx.y * 32;
    int tx = threadIdx.x & 31, ty = threadIdx.x >> 5;  // ty 0..7
    #pragma unroll
    for (int i = 0; i < 32; i += 8)
        tile[ty + i][tx] = W[(size_t)(k0 + ty + i) * Ntot + n0 + tx];
    __syncthreads();
    #pragma unroll
    for (int i = 0; i < 32; i += 8) {
        float v = tile[tx][ty + i];              // = W[k0+tx][n0+ty+i]
        out[(size_t)(n0 + ty + i) * KB + k0 + tx] = __float2half_rn(v);
    }
}

// ================== mma.sync fp16 GEMM, 128x128 CTA tile ===================
// C[M,Ntot] = A[M,512]fp16 @ B[Ntot,512]fp16^T + bias; output fp32 or fp16.
// 8 warps (2x4), warp tile 64x32, BK=64 (8 chunks), 2-stage cp.async.
// smem pitch 144B = 9 x 16B (odd multiple of 16B) -> conflict-free ldmatrix.
constexpr int BKC    = 64;                      // k per chunk
constexpr int NKC    = KB / BKC;                // 8 k-chunks
constexpr int PITCH  = 144;                     // bytes per smem row
constexpr int TILE_B = 128 * PITCH;             // 18432 bytes per tile
constexpr int STAGE_B = 2 * TILE_B;             // A + B = 36864
constexpr int GEMM_SMEM = 2 * STAGE_B;          // 73728 bytes

template <bool HOUT>
__global__ __launch_bounds__(256, 2) void gemm_mma_kernel(
    const __half* __restrict__ A, const __half* __restrict__ Bm,
    const float* __restrict__ bias, void* __restrict__ Cout, int Ntot)
{
    extern __shared__ __align__(16) __half smem[];

    const int tid  = threadIdx.x;
    const int lane = tid & 31;
    const int wid  = tid >> 5;
    const int wr   = wid & 1;     // warp row (0-1): 64 rows each
    const int wc   = wid >> 1;    // warp col (0-3): 32 cols each
    const size_t rowA0 = (size_t)blockIdx.y * 128;
    const size_t rowB0 = (size_t)blockIdx.x * 128;

    const __half* Abase = A + rowA0 * KB;
    const __half* Bbase = Bm + rowB0 * KB;

    const uint32_t s_base = smem_u32(smem);

    // copy: per stage 128 rows x 128B for A and B = 2048 x 16B chunks, 8/thread
    auto stage_copy = [&](int kc, int buf) {
        const uint32_t st = s_base + buf * STAGE_B;
        const int ko = kc * BKC;
        #pragma unroll
        for (int i = 0; i < 4; i++) {            // A: idx in [0,1024)
            int idx = tid + i * 256;
            int r = idx >> 3, c = idx & 7;
            const __half* g = Abase + (size_t)r * KB + ko + c * 8;
            CP_ASYNC16(st + (uint32_t)(r * PITCH + c * 16), g);
        }
        #pragma unroll
        for (int i = 0; i < 4; i++) {            // B
            int idx = tid + i * 256;
            int r = idx >> 3, c = idx & 7;
            const __half* g = Bbase + (size_t)r * KB + ko + c * 8;
            CP_ASYNC16(st + TILE_B + (uint32_t)(r * PITCH + c * 16), g);
        }
        CP_COMMIT();
    };

    float acc[4][4][4];
    #pragma unroll
    for (int i = 0; i < 4; i++)
        #pragma unroll
        for (int j = 0; j < 4; j++)
            #pragma unroll
            for (int k = 0; k < 4; k++) acc[i][j][k] = 0.f;

    // ldmatrix source coordinates
    const int a_row = wr * 64 + (lane & 7) + ((lane >> 3) & 1) * 8;
    const int a_k8  = ((lane >> 4) & 1) * 8;
    const int b_row = wc * 32 + (lane & 7) + ((lane >> 4) & 1) * 8;
    const int b_k8  = ((lane >> 3) & 1) * 8;

    stage_copy(0, 0);
    CP_WAIT0();
    __syncthreads();

    #pragma unroll 1
    for (int kc = 0; kc < NKC; kc++) {
        const int buf = kc & 1;
        if (kc + 1 < NKC) stage_copy(kc + 1, buf ^ 1);

        const uint32_t ab = s_base + buf * STAGE_B;
        const uint32_t bb = ab + TILE_B;
        #pragma unroll
        for (int ks = 0; ks < 4; ks++) {         // 4 x k16 per chunk
            uint32_t bfrg[2][4];
            #pragma unroll
            for (int nj2 = 0; nj2 < 2; nj2++)
                ldmatrix_x4(bfrg[nj2],
                    bb + (uint32_t)((b_row + nj2 * 16) * PITCH + (ks * 16 + b_k8) * 2));
            uint32_t afr[4][4];
            #pragma unroll
            for (int mi = 0; mi < 4; mi++)
                ldmatrix_x4(afr[mi],
                    ab + (uint32_t)((a_row + mi * 16) * PITCH + (ks * 16 + a_k8) * 2));
            #pragma unroll
            for (int mi = 0; mi < 4; mi++) {
                #pragma unroll
                for (int nj = 0; nj < 4; nj++) {
                    uint32_t b0 = bfrg[nj >> 1][(nj & 1) * 2];
                    uint32_t b1 = bfrg[nj >> 1][(nj & 1) * 2 + 1];
                    mma_f16(acc[mi][nj], afr[mi], b0, b1);
                }
            }
        }
        if (kc + 1 < NKC) CP_WAIT0();
        __syncthreads();
    }

    // epilogue: + bias; fp32 or fp16 stores
    #pragma unroll
    for (int mi = 0; mi < 4; mi++) {
        size_t r0 = rowA0 + wr * 64 + mi * 16 + (lane >> 2);
        size_t r1 = r0 + 8;
        #pragma unroll
        for (int nj = 0; nj < 4; nj++) {
            size_t col = rowB0 + wc * 32 + nj * 8 + (lane & 3) * 2;
            float b0 = __ldg(&bias[col]), b1 = __ldg(&bias[col + 1]);
            float c00 = acc[mi][nj][0] + b0, c01 = acc[mi][nj][1] + b1;
            float c10 = acc[mi][nj][2] + b0, c11 = acc[mi][nj][3] + b1;
            if (HOUT) {
                __half* Ch = (__half*)Cout;
                *(uint32_t*)(Ch + r0 * (size_t)Ntot + col) = packh(c00, c01);
                *(uint32_t*)(Ch + r1 * (size_t)Ntot + col) = packh(c10, c11);
            } else {
                float* Cf = (float*)Cout;
                float2 v0 = {c00, c01};
                float2 v1 = {c10, c11};
                *(float2*)(Cf + r0 * (size_t)Ntot + col) = v0;
                *(float2*)(Cf + r1 * (size_t)Ntot + col) = v1;
            }
        }
    }
}

__global__ void zero_attn_kernel()
{
    int i = blockIdx.x * blockDim.x + threadIdx.x;
    if (i < B_ * H_ * D_ * D_) g_attn[i] = 0.f;
}

// ========== attn[bh,d,e] = sum_n q~[n,d] k~[n,e], norms fused inline =======
// 256 threads, 4x4 tile/thread (proven R13 shape); TOKS=64 halves barriers.
__global__ __launch_bounds__(256) void attn_qk_kernel()
{
    constexpr int TOKS = 64;
    __shared__ __align__(16) float qs[TOKS][68];
    __shared__ __align__(16) float ks[TOKS][68];
    const int tid = threadIdx.x;
    const int tx = tid & 15, ty = tid >> 4;
    const int bh = blockIdx.y, b = bh >> 3, hh = bh & 7;
    const int tok_base = blockIdx.x * 256;

    float acc[4][4];
    #pragma unroll
    for (int i = 0; i < 4; i++)
        #pragma unroll
        for (int j = 0; j < 4; j++) acc[i][j] = 0.f;

    for (int sub = 0; sub < 256; sub += TOKS) {
        #pragma unroll
        for (int it = 0; it < 4; it++) {
            int fid = tid + it * 256;          // 0..1023
            int tl = fid >> 4, d4 = fid & 15;
            int t = b * N_ + tok_base + sub + tl;
            const __half* base = g_qkvh + (size_t)t * C3 + hh * D_ + d4 * 4;
            uint2 qh = *(const uint2*)base;
            uint2 kh = *(const uint2*)(base + C_);
            float2 q01 = __half22float2(*(__half2*)&qh.x);
            float2 q23 = __half22float2(*(__half2*)&qh.y);
            float2 k01 = __half22float2(*(__half2*)&kh.x);
            float2 k23 = __half22float2(*(__half2*)&kh.y);
            float sq = q01.x * q01.x + q01.y * q01.y + q23.x * q23.x + q23.y * q23.y;
            float sk = k01.x * k01.x + k01.y * k01.y + k23.x * k23.x + k23.y * k23.y;
            #pragma unroll
            for (int o = 8; o; o >>= 1) {
                sq += __shfl_xor_sync(0xFFFFFFFFu, sq, o);
                sk += __shfl_xor_sync(0xFFFFFFFFu, sk, o);
            }
            float rq = 0.125f * rsqrtf(fmaxf(sq, 1e-12f));  // includes d^-0.5
            float rk = rsqrtf(fmaxf(sk, 1e-12f));
            float4 qv = {q01.x * rq, q01.y * rq, q23.x * rq, q23.y * rq};
            float4 kv = {k01.x * rk, k01.y * rk, k23.x * rk, k23.y * rk};
            *(float4*)&qs[tl][d4 * 4] = qv;
            *(float4*)&ks[tl][d4 * 4] = kv;
        }
        __syncthreads();
        #pragma unroll 4
        for (int tok = 0; tok < TOKS; tok++) {
            float4 qd = *(const float4*)&qs[tok][ty * 4];
            float4 ke = *(const float4*)&ks[tok][tx * 4];
            float rd[4] = {qd.x, qd.y, qd.z, qd.w};
            float re[4] = {ke.x, ke.y, ke.z, ke.w};
            #pragma unroll
            for (int i = 0; i < 4; i++)
                #pragma unroll
                for (int j = 0; j < 4; j++)
                    acc[i][j] = fmaf(rd[i], re[j], acc[i][j]);
        }
        __syncthreads();
    }
    float* out = g_attn + (size_t)bh * D_ * D_;
    #pragma unroll
    for (int i = 0; i < 4; i++)
        #pragma unroll
        for (int j = 0; j < 4; j++)
            atomicAdd(&out[(ty * 4 + i) * D_ + tx * 4 + j], acc[i][j]);
}

// == mid = v @ softmax(attn): warp-parallel fused softmax; fp16 out ==========
__global__ __launch_bounds__(256) void v_attn_kernel()
{
    __shared__ __align__(16) float at[D_][D_];
    __shared__ __align__(16) float vs[D_][D_];
    const int tid = threadIdx.x;
    const int lane = tid & 31;
    const int wrp  = tid >> 5;       // 8 warps
    const int bh = blockIdx.y, b = bh >> 3, hh = bh & 7;
    const int tok0 = blockIdx.x * 64;

    const float* ap = g_attn + (size_t)bh * D_ * D_;
    #pragma unroll
    for (int it = 0; it < 4; it++) {
        int fid = tid + it * 256;
        ((float4*)at)[fid] = ((const float4*)ap)[fid];
    }
    #pragma unroll
    for (int it = 0; it < 4; it++) {
        int fid = tid + it * 256;
        int tl = fid >> 4, d4 = fid & 15;
        int t = b * N_ + tok0 + tl;
        uint2 vh = *(const uint2*)(g_qkvh + (size_t)t * C3 + 2 * C_ + hh * D_ + d4 * 4);
        float2 v01 = __half22float2(*(__half2*)&vh.x);
        float2 v23 = __half22float2(*(__half2*)&vh.y);
        float4 vv = {v01.x, v01.y, v23.x, v23.y};
        *(float4*)&vs[tl][d4 * 4] = vv;
    }
    __syncthreads();

    // fused softmax: warp-per-row group, lanes parallel over e (conflict-free)
    #pragma unroll
    for (int i = 0; i < 8; i++) {
        int d = wrp * 8 + i;
        float e0 = at[d][lane], e1 = at[d][lane + 32];
        float m = fmaxf(e0, e1);
        #pragma unroll
        for (int o = 16; o; o >>= 1) m = fmaxf(m, __shfl_xor_sync(0xFFFFFFFFu, m, o));
        float x0 = __expf(e0 - m), x1 = __expf(e1 - m);
        float s = x0 + x1;
        #pragma unroll
        for (int o = 16; o; o >>= 1) s += __shfl_xor_sync(0xFFFFFFFFu, s, o);
        float inv = 1.f / s;
        at[d][lane]      = x0 * inv;
        at[d][lane + 32] = x1 * inv;
    }
    __syncthreads();

    const int rg = tid >> 4, cg = tid & 15;
    float acc[4][4];
    #pragma unroll
    for (int i = 0; i < 4; i++)
        #pragma unroll
        for (int j = 0; j < 4; j++) acc[i][j] = 0.f;

    #pragma unroll 8
    for (int d = 0; d < D_; d++) {
        float4 a4 = *(const float4*)&at[d][cg * 4];
        float ae[4] = {a4.x, a4.y, a4.z, a4.w};
        #pragma unroll
        for (int i = 0; i < 4; i++) {
            float va = vs[rg * 4 + i][d];
            #pragma unroll
            for (int j = 0; j < 4; j++)
                acc[i][j] = fmaf(va, ae[j], acc[i][j]);
        }
    }

    #pragma unroll
    for (int i = 0; i < 4; i++) {
        int t = b * N_ + tok0 + rg * 4 + i;
        uint2 hi;
        hi.x = packh(acc[i][0], acc[i][1]);
        hi.y = packh(acc[i][2], acc[i][3]);
        *(uint2*)(g_ms + (size_t)t * KB + hh * D_ + cg * 4) = hi;
    }
}

// ================================ launch ===================================
extern "C" void kernel_launch(void* const* d_in, const int* in_sizes, int n_in,
                              void* d_out, int out_size)
{
    const float* x      = (const float*)d_in[0];
    const float* w_qkv  = (const float*)d_in[1];
    const float* b_qkv  = (const float*)d_in[2];
    const float* w_proj = (const float*)d_in[3];
    const float* b_proj = (const float*)d_in[4];
    float* out = (float*)d_out;

    __half* xs; cudaGetSymbolAddress((void**)&xs, g_xs);
    __half* ms; cudaGetSymbolAddress((void**)&ms, g_ms);
    __half* wq; cudaGetSymbolAddress((void**)&wq, g_wq);
    __half* wp; cudaGetSymbolAddress((void**)&wp, g_wp);
    __half* qkvh; cudaGetSymbolAddress((void**)&qkvh, g_qkvh);

    cudaFuncSetAttribute(gemm_mma_kernel<true>,
                         cudaFuncAttributeMaxDynamicSharedMemorySize, GEMM_SMEM);
    cudaFuncSetAttribute(gemm_mma_kernel<false>,
                         cudaFuncAttributeMaxDynamicSharedMemorySize, GEMM_SMEM);

    // prep: fp16 conversions (+ zero logits, off the critical GEMM path)
    split_x_kernel<<<(MTOK * (C_ / 4)) / 256, 256>>>(x);
    split_w_kernel<<<dim3(C3 / 32, C_ / 32), 256>>>(w_qkv, wq, C3);
    split_w_kernel<<<dim3(C_ / 32, C_ / 32), 256>>>(w_proj, wp, C_);
    zero_attn_kernel<<<(B_ * H_ * D_ * D_ + 255) / 256, 256>>>();

    // qkv = x @ w_qkv + b_qkv  (fp16 mma.sync, fp16 output)
    gemm_mma_kernel<true><<<dim3(C3 / 128, MTOK / 128), 256, GEMM_SMEM>>>(
        xs, wq, b_qkv, qkvh, C3);

    attn_qk_kernel<<<dim3(N_ / 256, B_ * H_), 256>>>();
    v_attn_kernel<<<dim3(N_ / 64, B_ * H_), 256>>>();

    // out = mid @ w_proj + b_proj  (fp16 mma.sync, fp32 output)
    gemm_mma_kernel<false><<<dim3(C_ / 128, MTOK / 128), 256, GEMM_SMEM>>>(
        ms, wp, b_proj, out, C_);
}

// round 16
// speedup vs baseline: 1.0271x; 1.0241x over previous
#include <cuda_runtime.h>
#include <cuda_fp16.h>
#include <math.h>
#include <stdint.h>

// Shapes (fixed): x[8,4096,512] f32, w_qkv[512,1536], b_qkv[1536],
// w_proj[512,512], b_proj[512], out[8,4096,512] f32.
constexpr int B_   = 8;
constexpr int N_   = 4096;
constexpr int C_   = 512;
constexpr int H_   = 8;
constexpr int D_   = 64;
constexpr int MTOK = B_ * N_;   // 32768
constexpr int C3   = 3 * C_;    // 1536
constexpr int KB   = 512;       // GEMM K (fp16 operands both sides)

// ------------------------- device scratch (static) -------------------------
__device__ __half g_xs[(size_t)MTOK * KB];    // x   -> fp16   (A of qkv gemm)
__device__ __half g_ms[(size_t)MTOK * KB];    // mid -> fp16   (A of proj gemm)
__device__ __half g_wq[(size_t)C3 * KB];      // w_qkv^T  fp16 [n][k]
__device__ __half g_wp[(size_t)C_ * KB];      // w_proj^T fp16 [n][k]
__device__ __half g_qkvh[(size_t)MTOK * C3];  // qkv fp16 [tok][1536]
__device__ float g_attn[B_ * H_ * D_ * D_];   // raw logits (softmax fused in v_attn)

// ----------------------------- helpers ------------------------------------
__device__ __forceinline__ uint32_t smem_u32(const void* p) {
    uint32_t a;
    asm("{ .reg .u64 t; cvta.to.shared.u64 t, %1; cvt.u32.u64 %0, t; }"
        : "=r"(a) : "l"(p));
    return a;
}
__device__ __forceinline__ uint32_t packh(float a, float b) {
    __half2 p = __floats2half2_rn(a, b);
    return *(uint32_t*)&p;
}

#define CP_ASYNC16(dst_u32, src_ptr) \
    asm volatile("cp.async.cg.shared.global [%0], [%1], 16;" \
        :: "r"(dst_u32), "l"(src_ptr))
#define CP_COMMIT()  asm volatile("cp.async.commit_group;")
#define CP_WAIT0()   asm volatile("cp.async.wait_group 0;" ::: "memory")

__device__ __forceinline__ void ldmatrix_x4(uint32_t* r, uint32_t addr) {
    asm volatile("ldmatrix.sync.aligned.m8n8.x4.shared.b16 {%0,%1,%2,%3}, [%4];"
        : "=r"(r[0]), "=r"(r[1]), "=r"(r[2]), "=r"(r[3]) : "r"(addr));
}
__device__ __forceinline__ void mma_f16(float* c, const uint32_t* a,
                                        uint32_t b0, uint32_t b1) {
    asm volatile(
        "mma.sync.aligned.m16n8k16.row.col.f32.f16.f16.f32 "
        "{%0,%1,%2,%3}, {%4,%5,%6,%7}, {%8,%9}, {%0,%1,%2,%3};"
        : "+f"(c[0]), "+f"(c[1]), "+f"(c[2]), "+f"(c[3])
        : "r"(a[0]), "r"(a[1]), "r"(a[2]), "r"(a[3]), "r"(b0), "r"(b1));
}

// =========================== prep kernels ==================================
// x fp32 -> fp16
__global__ __launch_bounds__(256) void split_x_kernel(const float* __restrict__ x)
{
    size_t fid = (size_t)blockIdx.x * 256 + threadIdx.x;  // MTOK*128 float4s
    size_t t = fid >> 7;
    int c4 = (int)(fid & 127);
    float4 v = ((const float4*)x)[fid];
    uint2 hi;
    hi.x = packh(v.x, v.y); hi.y = packh(v.z, v.w);
    *(uint2*)(g_xs + t * KB + c4 * 4) = hi;
}

// Combined: transpose-convert BOTH weight matrices to fp16 [n][k] layout AND
// zero the logits accumulator. grid = (64, 16): x<48 -> w_qkv tile, else w_proj.
__global__ __launch_bounds__(256) void prep_w_kernel(const float* __restrict__ Wq,
                                                     const float* __restrict__ Wp)
{
    // zero g_attn: exactly 64*16*256 = 262144 threads = B_*H_*D_*D_ floats
    int zi = (blockIdx.y * gridDim.x + blockIdx.x) * 256 + threadIdx.x;
    g_attn[zi] = 0.f;

    __shared__ float tile[32][33];
    const int wq_tiles = C3 / 32;  // 48
    const bool is_q = (blockIdx.x < (unsigned)wq_tiles);
    const float* W = is_q ? Wq : Wp;
    __half* out = is_q ? g_wq : g_wp;
    const int Ntot = is_q ? C3 : C_;
    int n0 = (is_q ? blockIdx.x : blockIdx.x - wq_tiles) * 32;
    int k0 = blockIdx.y * 32;
    int tx = threadIdx.x & 31, ty = threadIdx.x >> 5;  // ty 0..7
    #pragma unroll
    for (int i = 0; i < 32; i += 8)
        tile[ty + i][tx] = W[(size_t)(k0 + ty + i) * Ntot + n0 + tx];
    __syncthreads();
    #pragma unroll
    for (int i = 0; i < 32; i += 8) {
        float v = tile[tx][ty + i];              // = W[k0+tx][n0+ty+i]
        out[(size_t)(n0 + ty + i) * KB + k0 + tx] = __float2half_rn(v);
    }
}

// ================== mma.sync fp16 GEMM, 128x128 CTA tile ===================
// C[M,Ntot] = A[M,512]fp16 @ B[Ntot,512]fp16^T + bias; output fp32 or fp16.
// 8 warps (2x4), warp tile 64x32, BK=64 (8 chunks), 2-stage cp.async.
// smem pitch 144B = 9 x 16B (odd multiple of 16B) -> conflict-free ldmatrix.
constexpr int BKC    = 64;                      // k per chunk
constexpr int NKC    = KB / BKC;                // 8 k-chunks
constexpr int PITCH  = 144;                     // bytes per smem row
constexpr int TILE_B = 128 * PITCH;             // 18432 bytes per tile
constexpr int STAGE_B = 2 * TILE_B;             // A + B = 36864
constexpr int GEMM_SMEM = 2 * STAGE_B;          // 73728 bytes

template <bool HOUT>
__global__ __launch_bounds__(256, 2) void gemm_mma_kernel(
    const __half* __restrict__ A, const __half* __restrict__ Bm,
    const float* __restrict__ bias, void* __restrict__ Cout, int Ntot)
{
    extern __shared__ __align__(16) __half smem[];

    const int tid  = threadIdx.x;
    const int lane = tid & 31;
    const int wid  = tid >> 5;
    const int wr   = wid & 1;     // warp row (0-1): 64 rows each
    const int wc   = wid >> 1;    // warp col (0-3): 32 cols each
    const size_t rowA0 = (size_t)blockIdx.y * 128;
    const size_t rowB0 = (size_t)blockIdx.x * 128;

    const __half* Abase = A + rowA0 * KB;
    const __half* Bbase = Bm + rowB0 * KB;

    const uint32_t s_base = smem_u32(smem);

    // copy: per stage 128 rows x 128B for A and B = 2048 x 16B chunks, 8/thread
    auto stage_copy = [&](int kc, int buf) {
        const uint32_t st = s_base + buf * STAGE_B;
        const int ko = kc * BKC;
        #pragma unroll
        for (int i = 0; i < 4; i++) {            // A: idx in [0,1024)
            int idx = tid + i * 256;
            int r = idx >> 3, c = idx & 7;
            const __half* g = Abase + (size_t)r * KB + ko + c * 8;
            CP_ASYNC16(st + (uint32_t)(r * PITCH + c * 16), g);
        }
        #pragma unroll
        for (int i = 0; i < 4; i++) {            // B
            int idx = tid + i * 256;
            int r = idx >> 3, c = idx & 7;
            const __half* g = Bbase + (size_t)r * KB + ko + c * 8;
            CP_ASYNC16(st + TILE_B + (uint32_t)(r * PITCH + c * 16), g);
        }
        CP_COMMIT();
    };

    float acc[4][4][4];
    #pragma unroll
    for (int i = 0; i < 4; i++)
        #pragma unroll
        for (int j = 0; j < 4; j++)
            #pragma unroll
            for (int k = 0; k < 4; k++) acc[i][j][k] = 0.f;

    // ldmatrix source coordinates
    const int a_row = wr * 64 + (lane & 7) + ((lane >> 3) & 1) * 8;
    const int a_k8  = ((lane >> 4) & 1) * 8;
    const int b_row = wc * 32 + (lane & 7) + ((lane >> 4) & 1) * 8;
    const int b_k8  = ((lane >> 3) & 1) * 8;

    stage_copy(0, 0);
    CP_WAIT0();
    __syncthreads();

    #pragma unroll 1
    for (int kc = 0; kc < NKC; kc++) {
        const int buf = kc & 1;
        if (kc + 1 < NKC) stage_copy(kc + 1, buf ^ 1);

        const uint32_t ab = s_base + buf * STAGE_B;
        const uint32_t bb = ab + TILE_B;
        #pragma unroll
        for (int ks = 0; ks < 4; ks++) {         // 4 x k16 per chunk
            uint32_t bfrg[2][4];
            #pragma unroll
            for (int nj2 = 0; nj2 < 2; nj2++)
                ldmatrix_x4(bfrg[nj2],
                    bb + (uint32_t)((b_row + nj2 * 16) * PITCH + (ks * 16 + b_k8) * 2));
            uint32_t afr[4][4];
            #pragma unroll
            for (int mi = 0; mi < 4; mi++)
                ldmatrix_x4(afr[mi],
                    ab + (uint32_t)((a_row + mi * 16) * PITCH + (ks * 16 + a_k8) * 2));
            #pragma unroll
            for (int mi = 0; mi < 4; mi++) {
                #pragma unroll
                for (int nj = 0; nj < 4; nj++) {
                    uint32_t b0 = bfrg[nj >> 1][(nj & 1) * 2];
                    uint32_t b1 = bfrg[nj >> 1][(nj & 1) * 2 + 1];
                    mma_f16(acc[mi][nj], afr[mi], b0, b1);
                }
            }
        }
        if (kc + 1 < NKC) CP_WAIT0();
        __syncthreads();
    }

    // epilogue: + bias; fp32 or fp16 stores
    #pragma unroll
    for (int mi = 0; mi < 4; mi++) {
        size_t r0 = rowA0 + wr * 64 + mi * 16 + (lane >> 2);
        size_t r1 = r0 + 8;
        #pragma unroll
        for (int nj = 0; nj < 4; nj++) {
            size_t col = rowB0 + wc * 32 + nj * 8 + (lane & 3) * 2;
            float b0 = __ldg(&bias[col]), b1 = __ldg(&bias[col + 1]);
            float c00 = acc[mi][nj][0] + b0, c01 = acc[mi][nj][1] + b1;
            float c10 = acc[mi][nj][2] + b0, c11 = acc[mi][nj][3] + b1;
            if (HOUT) {
                __half* Ch = (__half*)Cout;
                *(uint32_t*)(Ch + r0 * (size_t)Ntot + col) = packh(c00, c01);
                *(uint32_t*)(Ch + r1 * (size_t)Ntot + col) = packh(c10, c11);
            } else {
                float* Cf = (float*)Cout;
                float2 v0 = {c00, c01};
                float2 v1 = {c10, c11};
                *(float2*)(Cf + r0 * (size_t)Ntot + col) = v0;
                *(float2*)(Cf + r1 * (size_t)Ntot + col) = v1;
            }
        }
    }
}

// ========== attn[bh,d,e] = sum_n q~[n,d] k~[n,e], norms fused inline =======
// Exact R13 configuration: 256 threads, 4x4 tile/thread, TOKS=32.
__global__ __launch_bounds__(256) void attn_qk_kernel()
{
    constexpr int TOKS = 32;
    __shared__ __align__(16) float qs[TOKS][68];
    __shared__ __align__(16) float ks[TOKS][68];
    const int tid = threadIdx.x;
    const int tx = tid & 15, ty = tid >> 4;
    const int bh = blockIdx.y, b = bh >> 3, hh = bh & 7;
    const int tok_base = blockIdx.x * 256;

    float acc[4][4];
    #pragma unroll
    for (int i = 0; i < 4; i++)
        #pragma unroll
        for (int j = 0; j < 4; j++) acc[i][j] = 0.f;

    for (int sub = 0; sub < 256; sub += TOKS) {
        #pragma unroll
        for (int it = 0; it < 2; it++) {
            int fid = tid + it * 256;
            int tl = fid >> 4, d4 = fid & 15;
            int t = b * N_ + tok_base + sub + tl;
            const __half* base = g_qkvh + (size_t)t * C3 + hh * D_ + d4 * 4;
            uint2 qh = *(const uint2*)base;
            uint2 kh = *(const uint2*)(base + C_);
            float2 q01 = __half22float2(*(__half2*)&qh.x);
            float2 q23 = __half22float2(*(__half2*)&qh.y);
            float2 k01 = __half22float2(*(__half2*)&kh.x);
            float2 k23 = __half22float2(*(__half2*)&kh.y);
            float sq = q01.x * q01.x + q01.y * q01.y + q23.x * q23.x + q23.y * q23.y;
            float sk = k01.x * k01.x + k01.y * k01.y + k23.x * k23.x + k23.y * k23.y;
            #pragma unroll
            for (int o = 8; o; o >>= 1) {
                sq += __shfl_xor_sync(0xFFFFFFFFu, sq, o);
                sk += __shfl_xor_sync(0xFFFFFFFFu, sk, o);
            }
            float rq = 0.125f * rsqrtf(fmaxf(sq, 1e-12f));  // includes d^-0.5
            float rk = rsqrtf(fmaxf(sk, 1e-12f));
            float4 qv = {q01.x * rq, q01.y * rq, q23.x * rq, q23.y * rq};
            float4 kv = {k01.x * rk, k01.y * rk, k23.x * rk, k23.y * rk};
            *(float4*)&qs[tl][d4 * 4] = qv;
            *(float4*)&ks[tl][d4 * 4] = kv;
        }
        __syncthreads();
        #pragma unroll 4
        for (int tok = 0; tok < TOKS; tok++) {
            float4 qd = *(const float4*)&qs[tok][ty * 4];
            float4 ke = *(const float4*)&ks[tok][tx * 4];
            float rd[4] = {qd.x, qd.y, qd.z, qd.w};
            float re[4] = {ke.x, ke.y, ke.z, ke.w};
            #pragma unroll
            for (int i = 0; i < 4; i++)
                #pragma unroll
                for (int j = 0; j < 4; j++)
                    acc[i][j] = fmaf(rd[i], re[j], acc[i][j]);
        }
        __syncthreads();
    }
    float* out = g_attn + (size_t)bh * D_ * D_;
    #pragma unroll
    for (int i = 0; i < 4; i++)
        #pragma unroll
        for (int j = 0; j < 4; j++)
            atomicAdd(&out[(ty * 4 + i) * D_ + tx * 4 + j], acc[i][j]);
}

// == mid = v @ softmax(attn): warp-parallel fused softmax; fp16 out ==========
__global__ __launch_bounds__(256) void v_attn_kernel()
{
    __shared__ __align__(16) float at[D_][D_];
    __shared__ __align__(16) float vs[D_][D_];
    const int tid = threadIdx.x;
    const int lane = tid & 31;
    const int wrp  = tid >> 5;       // 8 warps
    const int bh = blockIdx.y, b = bh >> 3, hh = bh & 7;
    const int tok0 = blockIdx.x * 64;

    const float* ap = g_attn + (size_t)bh * D_ * D_;
    #pragma unroll
    for (int it = 0; it < 4; it++) {
        int fid = tid + it * 256;
        ((float4*)at)[fid] = ((const float4*)ap)[fid];
    }
    #pragma unroll
    for (int it = 0; it < 4; it++) {
        int fid = tid + it * 256;
        int tl = fid >> 4, d4 = fid & 15;
        int t = b * N_ + tok0 + tl;
        uint2 vh = *(const uint2*)(g_qkvh + (size_t)t * C3 + 2 * C_ + hh * D_ + d4 * 4);
        float2 v01 = __half22float2(*(__half2*)&vh.x);
        float2 v23 = __half22float2(*(__half2*)&vh.y);
        float4 vv = {v01.x, v01.y, v23.x, v23.y};
        *(float4*)&vs[tl][d4 * 4] = vv;
    }
    __syncthreads();

    // fused softmax: warp-per-row group, lanes parallel over e (conflict-free)
    #pragma unroll
    for (int i = 0; i < 8; i++) {
        int d = wrp * 8 + i;
        float e0 = at[d][lane], e1 = at[d][lane + 32];
        float m = fmaxf(e0, e1);
        #pragma unroll
        for (int o = 16; o; o >>= 1) m = fmaxf(m, __shfl_xor_sync(0xFFFFFFFFu, m, o));
        float x0 = __expf(e0 - m), x1 = __expf(e1 - m);
        float s = x0 + x1;
        #pragma unroll
        for (int o = 16; o; o >>= 1) s += __shfl_xor_sync(0xFFFFFFFFu, s, o);
        float inv = 1.f / s;
        at[d][lane]      = x0 * inv;
        at[d][lane + 32] = x1 * inv;
    }
    __syncthreads();

    const int rg = tid >> 4, cg = tid & 15;
    float acc[4][4];
    #pragma unroll
    for (int i = 0; i < 4; i++)
        #pragma unroll
        for (int j = 0; j < 4; j++) acc[i][j] = 0.f;

    #pragma unroll 8
    for (int d = 0; d < D_; d++) {
        float4 a4 = *(const float4*)&at[d][cg * 4];
        float ae[4] = {a4.x, a4.y, a4.z, a4.w};
        #pragma unroll
        for (int i = 0; i < 4; i++) {
            float va = vs[rg * 4 + i][d];
            #pragma unroll
            for (int j = 0; j < 4; j++)
                acc[i][j] = fmaf(va, ae[j], acc[i][j]);
        }
    }

    #pragma unroll
    for (int i = 0; i < 4; i++) {
        int t = b * N_ + tok0 + rg * 4 + i;
        uint2 hi;
        hi.x = packh(acc[i][0], acc[i][1]);
        hi.y = packh(acc[i][2], acc[i][3]);
        *(uint2*)(g_ms + (size_t)t * KB + hh * D_ + cg * 4) = hi;
    }
}

// ================================ launch ===================================
extern "C" void kernel_launch(void* const* d_in, const int* in_sizes, int n_in,
                              void* d_out, int out_size)
{
    const float* x      = (const float*)d_in[0];
    const float* w_qkv  = (const float*)d_in[1];
    const float* b_qkv  = (const float*)d_in[2];
    const float* w_proj = (const float*)d_in[3];
    const float* b_proj = (const float*)d_in[4];
    float* out = (float*)d_out;

    __half* xs; cudaGetSymbolAddress((void**)&xs, g_xs);
    __half* ms; cudaGetSymbolAddress((void**)&ms, g_ms);
    __half* wq; cudaGetSymbolAddress((void**)&wq, g_wq);
    __half* wp; cudaGetSymbolAddress((void**)&wp, g_wp);
    __half* qkvh; cudaGetSymbolAddress((void**)&qkvh, g_qkvh);

    cudaFuncSetAttribute(gemm_mma_kernel<true>,
                         cudaFuncAttributeMaxDynamicSharedMemorySize, GEMM_SMEM);
    cudaFuncSetAttribute(gemm_mma_kernel<false>,
                         cudaFuncAttributeMaxDynamicSharedMemorySize, GEMM_SMEM);

    // prep: x->fp16; both weights->fp16 transposed + zero logits (one launch)
    split_x_kernel<<<(MTOK * (C_ / 4)) / 256, 256>>>(x);
    prep_w_kernel<<<dim3(64, 16), 256>>>(w_qkv, w_proj);

    // qkv = x @ w_qkv + b_qkv  (fp16 mma.sync, fp16 output)
    gemm_mma_kernel<true><<<dim3(C3 / 128, MTOK / 128), 256, GEMM_SMEM>>>(
        xs, wq, b_qkv, qkvh, C3);

    attn_qk_kernel<<<dim3(N_ / 256, B_ * H_), 256>>>();
    v_attn_kernel<<<dim3(N_ / 64, B_ * H_), 256>>>();

    // out = mid @ w_proj + b_proj  (fp16 mma.sync, fp32 output)
    gemm_mma_kernel<false><<<dim3(C_ / 128, MTOK / 128), 256, GEMM_SMEM>>>(
        ms, wp, b_proj, out, C_);
}